// round 1
// baseline (speedup 1.0000x reference)
#include <cuda_runtime.h>
#include <cuda_bf16.h>

#define NUM_O 1024
#define WARPS_PER_BLOCK 8

__device__ __forceinline__ float ex2_approx(float x) {
    float y;
    asm("ex2.approx.ftz.f32 %0, %1;" : "=f"(y) : "f"(x));
    return y;
}

__global__ __launch_bounds__(WARPS_PER_BLOCK * 32)
void gaussian_rbf_kernel(const float* __restrict__ x,
                         const float* __restrict__ mus,
                         const float* __restrict__ log_sigmas,
                         float* __restrict__ out,
                         int rows)
{
    // Per-o precomputed coefficients:
    // arg(o,row) = sc[o]*xx + sg[o] + s0[o]*x0 + s1[o]*x1 + s2[o]*x2
    // where sc = -log2e / sigma^2, sg = sc*|mu|^2, sk = -2*sc*mu_k.
    // Then y = exp2(arg).
    __shared__ __align__(16) float sc[NUM_O];
    __shared__ __align__(16) float sg[NUM_O];
    __shared__ __align__(16) float s0[NUM_O];
    __shared__ __align__(16) float s1[NUM_O];
    __shared__ __align__(16) float s2[NUM_O];

    const float LOG2E = 1.4426950408889634f;

    for (int o = threadIdx.x; o < NUM_O; o += blockDim.x) {
        float m0 = mus[o * 3 + 0];
        float m1 = mus[o * 3 + 1];
        float m2 = mus[o * 3 + 2];
        float ls = log_sigmas[o];
        float inv_sig2 = __expf(-2.0f * ls);     // 1/sigma^2
        float c = -inv_sig2 * LOG2E;
        sc[o] = c;
        sg[o] = c * (m0 * m0 + m1 * m1 + m2 * m2);
        s0[o] = -2.0f * c * m0;
        s1[o] = -2.0f * c * m1;
        s2[o] = -2.0f * c * m2;
    }
    __syncthreads();

    const int warp = threadIdx.x >> 5;
    const int lane = threadIdx.x & 31;
    const int row = blockIdx.x * WARPS_PER_BLOCK + warp;
    if (row >= rows) return;

    const float x0 = __ldg(&x[row * 3 + 0]);
    const float x1 = __ldg(&x[row * 3 + 1]);
    const float x2 = __ldg(&x[row * 3 + 2]);
    const float xx = x0 * x0 + x1 * x1 + x2 * x2;

    float e[32];
    float sum = 0.0f;

    #pragma unroll
    for (int j = 0; j < 8; j++) {
        const int o = j * 128 + lane * 4;
        const float4 c4 = *reinterpret_cast<const float4*>(&sc[o]);
        const float4 g4 = *reinterpret_cast<const float4*>(&sg[o]);
        const float4 a4 = *reinterpret_cast<const float4*>(&s0[o]);
        const float4 b4 = *reinterpret_cast<const float4*>(&s1[o]);
        const float4 d4 = *reinterpret_cast<const float4*>(&s2[o]);

        float arg0 = fmaf(c4.x, xx, g4.x);
        float arg1 = fmaf(c4.y, xx, g4.y);
        float arg2 = fmaf(c4.z, xx, g4.z);
        float arg3 = fmaf(c4.w, xx, g4.w);
        arg0 = fmaf(a4.x, x0, arg0); arg1 = fmaf(a4.y, x0, arg1);
        arg2 = fmaf(a4.z, x0, arg2); arg3 = fmaf(a4.w, x0, arg3);
        arg0 = fmaf(b4.x, x1, arg0); arg1 = fmaf(b4.y, x1, arg1);
        arg2 = fmaf(b4.z, x1, arg2); arg3 = fmaf(b4.w, x1, arg3);
        arg0 = fmaf(d4.x, x2, arg0); arg1 = fmaf(d4.y, x2, arg1);
        arg2 = fmaf(d4.z, x2, arg2); arg3 = fmaf(d4.w, x2, arg3);

        const float v0 = ex2_approx(arg0);
        const float v1 = ex2_approx(arg1);
        const float v2 = ex2_approx(arg2);
        const float v3 = ex2_approx(arg3);

        e[j * 4 + 0] = v0; e[j * 4 + 1] = v1;
        e[j * 4 + 2] = v2; e[j * 4 + 3] = v3;
        sum += (v0 + v1) + (v2 + v3);
    }

    // Warp reduction for row sum
    #pragma unroll
    for (int off = 16; off > 0; off >>= 1)
        sum += __shfl_xor_sync(0xFFFFFFFFu, sum, off);

    const float r = 1.0f / sum;

    float* __restrict__ orow = out + (size_t)row * NUM_O;
    #pragma unroll
    for (int j = 0; j < 8; j++) {
        const int o = j * 128 + lane * 4;
        float4 v;
        v.x = e[j * 4 + 0] * r;
        v.y = e[j * 4 + 1] * r;
        v.z = e[j * 4 + 2] * r;
        v.w = e[j * 4 + 3] * r;
        *reinterpret_cast<float4*>(&orow[o]) = v;
    }
}

extern "C" void kernel_launch(void* const* d_in, const int* in_sizes, int n_in,
                              void* d_out, int out_size) {
    const float* x          = (const float*)d_in[0];  // (B,S,3)
    const float* mus        = (const float*)d_in[1];  // (1024,3)
    const float* log_sigmas = (const float*)d_in[2];  // (1024,)
    float* out = (float*)d_out;

    const int rows = in_sizes[0] / 3;  // B*S = 32768
    const int blocks = (rows + WARPS_PER_BLOCK - 1) / WARPS_PER_BLOCK;
    gaussian_rbf_kernel<<<blocks, WARPS_PER_BLOCK * 32>>>(x, mus, log_sigmas, out, rows);
}

// round 2
// speedup vs baseline: 1.4211x; 1.4211x over previous
#include <cuda_runtime.h>
#include <cuda_bf16.h>

#define NUM_O 1024
#define WARPS_PER_BLOCK 8
#define ROWS_PER_WARP 4
#define ROWS_PER_BLOCK (WARPS_PER_BLOCK * ROWS_PER_WARP)

__device__ __forceinline__ float ex2_approx(float x) {
    float y;
    asm("ex2.approx.ftz.f32 %0, %1;" : "=f"(y) : "f"(x));
    return y;
}

__global__ __launch_bounds__(WARPS_PER_BLOCK * 32, 4)
void gaussian_rbf_kernel(const float* __restrict__ x,
                         const float* __restrict__ mus,
                         const float* __restrict__ log_sigmas,
                         float* __restrict__ out,
                         int rows)
{
    // Per-o coefficients: arg(o,row) = sc[o]*xx + sg[o] + s0[o]*x0 + s1[o]*x1 + s2[o]*x2
    // sc = -log2e/sigma^2, sg = sc*|mu|^2, sk = -2*sc*mu_k.  y = exp2(arg).
    __shared__ __align__(16) float sc[NUM_O];
    __shared__ __align__(16) float sg[NUM_O];
    __shared__ __align__(16) float s0[NUM_O];
    __shared__ __align__(16) float s1[NUM_O];
    __shared__ __align__(16) float s2[NUM_O];

    const float LOG2E = 1.4426950408889634f;

    for (int o = threadIdx.x; o < NUM_O; o += blockDim.x) {
        float m0 = mus[o * 3 + 0];
        float m1 = mus[o * 3 + 1];
        float m2 = mus[o * 3 + 2];
        float ls = log_sigmas[o];
        float inv_sig2 = __expf(-2.0f * ls);
        float c = -inv_sig2 * LOG2E;
        sc[o] = c;
        sg[o] = c * (m0 * m0 + m1 * m1 + m2 * m2);
        s0[o] = -2.0f * c * m0;
        s1[o] = -2.0f * c * m1;
        s2[o] = -2.0f * c * m2;
    }
    __syncthreads();

    const int warp = threadIdx.x >> 5;
    const int lane = threadIdx.x & 31;
    const int rbase = blockIdx.x * ROWS_PER_BLOCK + warp * ROWS_PER_WARP;

    // Load per-row x values (4 rows per warp). Clamp for safety; stores predicated.
    float x0[ROWS_PER_WARP], x1[ROWS_PER_WARP], x2[ROWS_PER_WARP], xx[ROWS_PER_WARP];
    #pragma unroll
    for (int r = 0; r < ROWS_PER_WARP; r++) {
        int row = rbase + r;
        int rc = row < rows ? row : (rows - 1);
        x0[r] = __ldg(&x[rc * 3 + 0]);
        x1[r] = __ldg(&x[rc * 3 + 1]);
        x2[r] = __ldg(&x[rc * 3 + 2]);
        xx[r] = x0[r] * x0[r] + x1[r] * x1[r] + x2[r] * x2[r];
    }

    // ---- Pass 1: row sums (no e storage) ----
    float sum[ROWS_PER_WARP] = {0.f, 0.f, 0.f, 0.f};

    #pragma unroll 2
    for (int j = 0; j < 8; j++) {
        const int o = j * 128 + lane * 4;
        const float4 c4 = *reinterpret_cast<const float4*>(&sc[o]);
        const float4 g4 = *reinterpret_cast<const float4*>(&sg[o]);
        const float4 a4 = *reinterpret_cast<const float4*>(&s0[o]);
        const float4 b4 = *reinterpret_cast<const float4*>(&s1[o]);
        const float4 d4 = *reinterpret_cast<const float4*>(&s2[o]);

        #pragma unroll
        for (int r = 0; r < ROWS_PER_WARP; r++) {
            float a0 = fmaf(c4.x, xx[r], g4.x);
            float a1 = fmaf(c4.y, xx[r], g4.y);
            float a2 = fmaf(c4.z, xx[r], g4.z);
            float a3 = fmaf(c4.w, xx[r], g4.w);
            a0 = fmaf(a4.x, x0[r], a0); a1 = fmaf(a4.y, x0[r], a1);
            a2 = fmaf(a4.z, x0[r], a2); a3 = fmaf(a4.w, x0[r], a3);
            a0 = fmaf(b4.x, x1[r], a0); a1 = fmaf(b4.y, x1[r], a1);
            a2 = fmaf(b4.z, x1[r], a2); a3 = fmaf(b4.w, x1[r], a3);
            a0 = fmaf(d4.x, x2[r], a0); a1 = fmaf(d4.y, x2[r], a1);
            a2 = fmaf(d4.z, x2[r], a2); a3 = fmaf(d4.w, x2[r], a3);
            float v0 = ex2_approx(a0);
            float v1 = ex2_approx(a1);
            float v2 = ex2_approx(a2);
            float v3 = ex2_approx(a3);
            sum[r] += (v0 + v1) + (v2 + v3);
        }
    }

    // Warp reductions (one per row)
    float rcp[ROWS_PER_WARP];
    #pragma unroll
    for (int r = 0; r < ROWS_PER_WARP; r++) {
        float s = sum[r];
        #pragma unroll
        for (int off = 16; off > 0; off >>= 1)
            s += __shfl_xor_sync(0xFFFFFFFFu, s, off);
        rcp[r] = 1.0f / s;
    }

    // ---- Pass 2: recompute, scale, store ----
    #pragma unroll 2
    for (int j = 0; j < 8; j++) {
        const int o = j * 128 + lane * 4;
        const float4 c4 = *reinterpret_cast<const float4*>(&sc[o]);
        const float4 g4 = *reinterpret_cast<const float4*>(&sg[o]);
        const float4 a4 = *reinterpret_cast<const float4*>(&s0[o]);
        const float4 b4 = *reinterpret_cast<const float4*>(&s1[o]);
        const float4 d4 = *reinterpret_cast<const float4*>(&s2[o]);

        #pragma unroll
        for (int r = 0; r < ROWS_PER_WARP; r++) {
            int row = rbase + r;
            if (row >= rows) break;
            float a0 = fmaf(c4.x, xx[r], g4.x);
            float a1 = fmaf(c4.y, xx[r], g4.y);
            float a2 = fmaf(c4.z, xx[r], g4.z);
            float a3 = fmaf(c4.w, xx[r], g4.w);
            a0 = fmaf(a4.x, x0[r], a0); a1 = fmaf(a4.y, x0[r], a1);
            a2 = fmaf(a4.z, x0[r], a2); a3 = fmaf(a4.w, x0[r], a3);
            a0 = fmaf(b4.x, x1[r], a0); a1 = fmaf(b4.y, x1[r], a1);
            a2 = fmaf(b4.z, x1[r], a2); a3 = fmaf(b4.w, x1[r], a3);
            a0 = fmaf(d4.x, x2[r], a0); a1 = fmaf(d4.y, x2[r], a1);
            a2 = fmaf(d4.z, x2[r], a2); a3 = fmaf(d4.w, x2[r], a3);
            float4 v;
            v.x = ex2_approx(a0) * rcp[r];
            v.y = ex2_approx(a1) * rcp[r];
            v.z = ex2_approx(a2) * rcp[r];
            v.w = ex2_approx(a3) * rcp[r];
            *reinterpret_cast<float4*>(&out[(size_t)row * NUM_O + o]) = v;
        }
    }
}

extern "C" void kernel_launch(void* const* d_in, const int* in_sizes, int n_in,
                              void* d_out, int out_size) {
    const float* x          = (const float*)d_in[0];  // (B,S,3)
    const float* mus        = (const float*)d_in[1];  // (1024,3)
    const float* log_sigmas = (const float*)d_in[2];  // (1024,)
    float* out = (float*)d_out;

    const int rows = in_sizes[0] / 3;  // B*S
    const int blocks = (rows + ROWS_PER_BLOCK - 1) / ROWS_PER_BLOCK;
    gaussian_rbf_kernel<<<blocks, WARPS_PER_BLOCK * 32>>>(x, mus, log_sigmas, out, rows);
}